// round 1
// baseline (speedup 1.0000x reference)
#include <cuda_runtime.h>
#include <cuda_bf16.h>

// Problem constants (from reference)
#define V_SZ     32000
#define D_SZ     5120
#define T_SZ     32
#define B_SZ     4
#define S_SZ     2048
#define VIS_DIM  768
#define N_SHARED (V_SZ + 2)          // 32002

#define D_CHUNK  1024                // floats per block (5 chunks cover D=5120)
#define THREADS  256                 // 256 threads * float4 = 1024 floats

__global__ __launch_bounds__(THREADS)
void myembed_fused_kernel(const int*   __restrict__ text,     // [B*S]
                          const float* __restrict__ vis,      // [B, T, VIS_DIM]
                          const float* __restrict__ weight,   // [V, D]
                          const float* __restrict__ fig,      // [2, D]
                          const float* __restrict__ fc_w,     // [VIS_DIM, D]
                          const float* __restrict__ fc_b,     // [D]
                          float*       __restrict__ out)      // [B, S, D]
{
    __shared__ float s_vis[VIS_DIM];

    const int tok = blockIdx.x;          // 0 .. B*S-1
    const int d0  = blockIdx.y * D_CHUNK;
    const int tid = threadIdx.x;
    const int d   = d0 + tid * 4;

    const int id = text[tok];
    float4* out4 = (float4*)(out + (size_t)tok * D_SZ + d);

    if (id < N_SHARED) {
        // ---- shared row: coalesced 4KB copy per block ----
        int idx = id < N_SHARED - 1 ? id : N_SHARED - 1;   // min(id, 32001)
        const float* src = (idx < V_SZ) ? (weight + (size_t)idx * D_SZ)
                                        : (fig    + (size_t)(idx - V_SZ) * D_SZ);
        *out4 = __ldg((const float4*)(src + d));
    } else {
        // ---- vision token: compute fc(vision_x) slice on the fly ----
        int tv = id - N_SHARED;
        if (tv > T_SZ - 1) tv = T_SZ - 1;                  // clip (matches reference)
        if (tv < 0)        tv = 0;
        const int b = tok / S_SZ;
        const float* vrow = vis + ((size_t)b * T_SZ + tv) * VIS_DIM;

        // stage vision row in smem (768 floats, 3 per thread)
        for (int i = tid; i < VIS_DIM; i += THREADS) s_vis[i] = vrow[i];
        __syncthreads();

        float4 acc = __ldg((const float4*)(fc_b + d));
        const float4* w4 = (const float4*)(fc_w + d);      // row stride = D_SZ/4 float4s

        #pragma unroll 4
        for (int k = 0; k < VIS_DIM; k++) {
            float  a = s_vis[k];
            float4 w = __ldg(&w4[(size_t)k * (D_SZ / 4)]);
            acc.x = fmaf(a, w.x, acc.x);
            acc.y = fmaf(a, w.y, acc.y);
            acc.z = fmaf(a, w.z, acc.z);
            acc.w = fmaf(a, w.w, acc.w);
        }
        *out4 = acc;
    }
}

extern "C" void kernel_launch(void* const* d_in, const int* in_sizes, int n_in,
                              void* d_out, int out_size)
{
    const int*   text   = (const int*)  d_in[0];  // [B,S] int32
    const float* vis    = (const float*)d_in[1];  // [B,T,VIS_DIM]
    const float* weight = (const float*)d_in[2];  // [V,D]
    const float* fig    = (const float*)d_in[3];  // [2,D]
    const float* fc_w   = (const float*)d_in[4];  // [VIS_DIM,D]
    const float* fc_b   = (const float*)d_in[5];  // [D]
    float*       out    = (float*)d_out;

    dim3 grid(B_SZ * S_SZ, D_SZ / D_CHUNK);       // 8192 x 5 = 40960 blocks
    myembed_fused_kernel<<<grid, THREADS>>>(text, vis, weight, fig, fc_w, fc_b, out);
}

// round 2
// speedup vs baseline: 1.9396x; 1.9396x over previous
#include <cuda_runtime.h>
#include <cuda_bf16.h>

// Problem constants (from reference)
#define V_SZ     32000
#define D_SZ     5120
#define T_SZ     32
#define B_SZ     4
#define S_SZ     2048
#define VIS_DIM  768
#define N_SHARED (V_SZ + 2)            // 32002

#define THREADS  256
#define NF4      (D_SZ / 4)            // 1280 float4 per row
#define F4_PER_T (NF4 / THREADS)       // 5 float4 per thread (copy path)
#define VCHUNK   512                   // floats per vision block
#define NVCHUNK  (D_SZ / VCHUNK)       // 10 vision chunks

__global__ __launch_bounds__(THREADS)
void embed_kernel(const int*   __restrict__ text,     // [B*S]
                  const float* __restrict__ vis,      // [B, T, VIS_DIM]
                  const float* __restrict__ weight,   // [V, D]
                  const float* __restrict__ fig,      // [2, D]
                  const float* __restrict__ fc_w,     // [VIS_DIM, D]
                  const float* __restrict__ fc_b,     // [D]
                  float*       __restrict__ out)      // [B, S, D]
{
    const int tok  = blockIdx.y;          // token index, 0..8191
    const int role = blockIdx.x;          // 0 = copy, 1..NVCHUNK = vision chunk
    const int tid  = threadIdx.x;

    const int  id         = __ldg(&text[tok]);
    const bool shared_tok = (id < N_SHARED);

    if (role == 0) {
        // ================= shared-row copy path =================
        if (!shared_tok) return;

        int idx = id < N_SHARED - 1 ? id : N_SHARED - 1;      // min(id, 32001)
        const float4* src = (const float4*)((idx < V_SZ)
                              ? (weight + (size_t)idx * D_SZ)
                              : (fig    + (size_t)(idx - V_SZ) * D_SZ));
        float4* dst = (float4*)(out + (size_t)tok * D_SZ);

        // batched loads (MLP=5), then batched stores — all coalesced
        float4 r0 = __ldcs(src + tid);
        float4 r1 = __ldcs(src + tid + 1 * THREADS);
        float4 r2 = __ldcs(src + tid + 2 * THREADS);
        float4 r3 = __ldcs(src + tid + 3 * THREADS);
        float4 r4 = __ldcs(src + tid + 4 * THREADS);
        __stcs(dst + tid,               r0);
        __stcs(dst + tid + 1 * THREADS, r1);
        __stcs(dst + tid + 2 * THREADS, r2);
        __stcs(dst + tid + 3 * THREADS, r3);
        __stcs(dst + tid + 4 * THREADS, r4);
    } else {
        // ================= vision projection path =================
        if (shared_tok) return;

        __shared__ float s_vis[VIS_DIM];

        int tv = id - N_SHARED;
        if (tv > T_SZ - 1) tv = T_SZ - 1;                     // clip, matches ref
        if (tv < 0)        tv = 0;
        const int b = tok / S_SZ;
        const float* vrow = vis + ((size_t)b * T_SZ + tv) * VIS_DIM;

        // stage vision row (768 floats, 3 per thread)
        for (int i = tid; i < VIS_DIM; i += THREADS) s_vis[i] = vrow[i];
        __syncthreads();

        // each thread computes 2 adjacent output columns over k = 0..767
        const int col = (role - 1) * VCHUNK + tid * 2;
        const float2* w2 = (const float2*)(fc_w + col);       // row stride D_SZ/2 float2
        float2 acc = *(const float2*)(fc_b + col);

        #pragma unroll 8
        for (int k = 0; k < VIS_DIM; k++) {
            float  a = s_vis[k];
            float2 w = __ldg(&w2[(size_t)k * (D_SZ / 2)]);
            acc.x = fmaf(a, w.x, acc.x);
            acc.y = fmaf(a, w.y, acc.y);
        }
        *(float2*)(out + (size_t)tok * D_SZ + col) = acc;
    }
}

extern "C" void kernel_launch(void* const* d_in, const int* in_sizes, int n_in,
                              void* d_out, int out_size)
{
    const int*   text   = (const int*)  d_in[0];  // [B,S] int32
    const float* vis    = (const float*)d_in[1];  // [B,T,VIS_DIM]
    const float* weight = (const float*)d_in[2];  // [V,D]
    const float* fig    = (const float*)d_in[3];  // [2,D]
    const float* fc_w   = (const float*)d_in[4];  // [VIS_DIM,D]
    const float* fc_b   = (const float*)d_in[5];  // [D]
    float*       out    = (float*)d_out;

    // x-fastest ordering: a token's copy block and its vision chunks are
    // adjacent in schedule order -> vision blocks never start late.
    dim3 grid(1 + NVCHUNK, B_SZ * S_SZ);          // 11 x 8192
    embed_kernel<<<grid, THREADS>>>(text, vis, weight, fig, fc_w, fc_b, out);
}